// round 11
// baseline (speedup 1.0000x reference)
#include <cuda_runtime.h>
#include <cuda_fp16.h>
#include <cstdint>

#define TOK 2048
#define HD  1536
#define ID  4096
#define NE  8      // 2 shared + 6 routed
#define ER  6
#define N2  (2*ID)   // interleaved gate/up width = 8192

// ---------------- device scratch (static, no allocations) ----------------
__device__ __align__(256) __half g_x16[(size_t)TOK*HD];
__device__ __align__(256) __half g_wgu[(size_t)NE*HD*N2];   // [e][H][2*ID] interleaved
__device__ __align__(256) __half g_wd [(size_t)NE*ID*HD];
__device__ __align__(256) __half g_h  [(size_t)NE*TOK*ID];  // gathered h per expert slot
__device__ int   g_cnt[ER];
__device__ int   g_tok[ER*TOK];
__device__ float g_wslot[ER*TOK];
// persistent-queue state
__device__ int   g_mte[128];     // m-tile -> expert        (GEMM2)
__device__ int   g_mtm[128];     // m-tile -> mBase         (GEMM2)
__device__ int   g_nmt;
__device__ int   g_eoff[NE+1];   // GEMM1 per-expert item offsets
__device__ int   g_ctr[2];
__device__ int   g_sflag[NE*64]; // wgu strip-converted flags

#define NWORK 304          // persistent CTAs (2 per SM on 152 SMs)
#define WDCH  768          // Wd convert chunks appended to GEMM1 queue
#define CHF4  16384        // float4 groups per chunk (768*16384 = 8*ID*HD/4 exactly)
#define NS4   (2L*ID*HD/4) // float4 groups in shared Wd (divisible by CHF4)

__device__ __forceinline__ unsigned h2u(__half2 h) {
    return *reinterpret_cast<unsigned*>(&h);
}

// ---------------- x fp32 -> fp16 (+ inline init of counters/flags) ----------------
__global__ void k_cvt_x(const float* __restrict__ src, long n8) {
    if (blockIdx.x == 0) {
        if (threadIdx.x < ER) g_cnt[threadIdx.x] = 0;
        for (int f = threadIdx.x; f < NE*64; f += blockDim.x) g_sflag[f] = 0;
    }
    const float4* s4 = (const float4*)src;
    uint4* d4 = (uint4*)g_x16;
    long i = (long)blockIdx.x*blockDim.x + threadIdx.x;
    long stride = (long)gridDim.x*blockDim.x;
    for (; i < n8; i += stride) {
        float4 a = s4[2*i], b = s4[2*i+1];
        uint4 o;
        o.x = h2u(__floats2half2_rn(a.x, a.y));
        o.y = h2u(__floats2half2_rn(a.z, a.w));
        o.z = h2u(__floats2half2_rn(b.x, b.y));
        o.w = h2u(__floats2half2_rn(b.z, b.w));
        d4[i] = o;
    }
}

// ---------------- router: warp per token, builds per-expert lists ----------------
__global__ void k_router(const float* __restrict__ x, const float* __restrict__ Wr,
                         const float* __restrict__ rb) {
    int t = (blockIdx.x*blockDim.x + threadIdx.x) >> 5;
    int lane = threadIdx.x & 31;
    if (t >= TOK) return;
    const float* xr = x + (size_t)t*HD;
    float acc[ER];
#pragma unroll
    for (int e = 0; e < ER; e++) acc[e] = 0.f;
    for (int h = lane; h < HD; h += 32) {
        float xv = xr[h];
#pragma unroll
        for (int e = 0; e < ER; e++) acc[e] = fmaf(xv, Wr[h*ER + e], acc[e]);
    }
#pragma unroll
    for (int e = 0; e < ER; e++) {
#pragma unroll
        for (int o = 16; o; o >>= 1) acc[e] += __shfl_xor_sync(0xffffffffu, acc[e], o);
    }
    if (lane == 0) {
#pragma unroll
        for (int e = 0; e < ER; e++) acc[e] += rb[e];
        float m = acc[0];
#pragma unroll
        for (int e = 1; e < ER; e++) m = fmaxf(m, acc[e]);
        float p[ER];
#pragma unroll
        for (int e = 0; e < ER; e++) p[e] = expf(acc[e] - m);
        int i0 = 0;
#pragma unroll
        for (int e = 1; e < ER; e++) if (p[e] > p[i0]) i0 = e;
        int i1 = (i0 == 0) ? 1 : 0;
#pragma unroll
        for (int e = 0; e < ER; e++) if (e != i0 && p[e] > p[i1]) i1 = e;
        float s = p[i0] + p[i1];
        int s0 = atomicAdd(&g_cnt[i0], 1);
        g_tok[i0*TOK + s0] = t;  g_wslot[i0*TOK + s0] = p[i0]/s;
        int s1 = atomicAdd(&g_cnt[i1], 1);
        g_tok[i1*TOK + s1] = t;  g_wslot[i1*TOK + s1] = p[i1]/s;
    }
}

// ---------------- planner ----------------
#define BM 128
__global__ void k_plan() {
    if (threadIdx.x == 0) {
        int nm = 0, off = 0;
        g_eoff[0] = 0;
        for (int e = 0; e < NE; e++) {
            int cnt = (e < 2) ? TOK : g_cnt[e-2];
            int nmtE = (cnt + BM - 1) / BM;
            for (int k = 0; k < nmtE; k++) { g_mte[nm] = e; g_mtm[nm] = k*BM; nm++; }
            off += 64 + nmtE*64;          // 64 convert items + tiles (strip-outer)
            g_eoff[e+1] = off;
        }
        g_nmt = nm;
        g_ctr[0] = 0;
        g_ctr[1] = 0;
    }
}

// ---------------- GEMM (mma.sync m16n8k16 fp16, fp32 accum) ----------------
#define BN 128
#define BK 64
#define PA 72
#define PB 136
#define ASTG (BM*PA)            // halves per A stage = 9216
#define BSTG (BK*PB)            // halves per B stage = 8704
#define STGH (ASTG+BSTG)        // halves per stage   = 17920
#define NSTAGE 3
#define SMEMSZ (NSTAGE*STGH*2)  // 107520 bytes

__device__ __forceinline__ void cpa16(uint32_t s, const void* g) {
    asm volatile("cp.async.cg.shared.global [%0], [%1], 16;\n" :: "r"(s), "l"(g));
}
__device__ __forceinline__ void ldm4(uint32_t& r0, uint32_t& r1, uint32_t& r2, uint32_t& r3, uint32_t a) {
    asm volatile("ldmatrix.sync.aligned.m8n8.x4.shared.b16 {%0,%1,%2,%3}, [%4];"
                 : "=r"(r0), "=r"(r1), "=r"(r2), "=r"(r3) : "r"(a));
}
__device__ __forceinline__ void ldm4t(uint32_t& r0, uint32_t& r1, uint32_t& r2, uint32_t& r3, uint32_t a) {
    asm volatile("ldmatrix.sync.aligned.m8n8.x4.trans.shared.b16 {%0,%1,%2,%3}, [%4];"
                 : "=r"(r0), "=r"(r1), "=r"(r2), "=r"(r3) : "r"(a));
}
__device__ __forceinline__ void mma16816(float* c, const uint32_t* a, uint32_t b0, uint32_t b1) {
    asm volatile("mma.sync.aligned.m16n8k16.row.col.f32.f16.f16.f32 "
                 "{%0,%1,%2,%3}, {%4,%5,%6,%7}, {%8,%9}, {%0,%1,%2,%3};"
                 : "+f"(c[0]), "+f"(c[1]), "+f"(c[2]), "+f"(c[3])
                 : "r"(a[0]), "r"(a[1]), "r"(a[2]), "r"(a[3]), "r"(b0), "r"(b1));
}
__device__ __forceinline__ void redv2(float* p, float a, float b) {
    asm volatile("red.global.add.v2.f32 [%0], {%1, %2};" :: "l"(p), "f"(a), "f"(b) : "memory");
}

// Persistent work-queue GEMM.
// MODE 1 queue (per expert e): [64 wgu-convert strip items][tiles strip-outer], then WDCH Wd chunks.
// MODE 2 queue: down-proj tiles, red.add scatter into out.
template<int MODE>
__global__ void __launch_bounds__(256, 2) k_gemm(float* __restrict__ outp,
                                                 const float* __restrict__ wdS,
                                                 const float* __restrict__ wdR,
                                                 const float* __restrict__ wgS,
                                                 const float* __restrict__ wuS,
                                                 const float* __restrict__ wgR,
                                                 const float* __restrict__ wuR) {
    extern __shared__ __half sh[];
    __shared__ int s_item;
    const int tid = threadIdx.x;
    const int wid = tid >> 5, lane = tid & 31;
    const int wm = wid >> 2, wn = wid & 3;
    const uint32_t sbase = (uint32_t)__cvta_generic_to_shared(sh);

    constexpr int K     = (MODE == 1) ? HD : ID;
    constexpr int nIter = K / BK;

    const int nTot = (MODE == 1) ? g_eoff[NE] + WDCH : g_nmt * (HD/BN);

    // per-thread load coords (tid-only; hoisted out of the work loop)
    int aR[4], aC[4], bR[4], bC[4];
#pragma unroll
    for (int i = 0; i < 4; i++) {
        int q = tid + 256*i;
        aR[i] = q >> 3;  aC[i] = (q & 7) * 8;
        bR[i] = q >> 4;  bC[i] = (q & 15) * 8;
    }

    for (;;) {
        if (tid == 0) s_item = atomicAdd(&g_ctr[MODE-1], 1);
        __syncthreads();                       // publish s_item; also guards smem reuse
        const int item = s_item;
        if (item >= nTot) return;

        // -------- decode --------
        int e, mBase = 0, bx = 0, cnt = 0;
        bool isTile = true, isWd = false, isCvt = false;
        if (MODE == 1) {
            if (item >= g_eoff[NE]) { isWd = true; isTile = false; }
            else {
                e = 0;
                while (item >= g_eoff[e+1]) e++;
                int local = item - g_eoff[e];
                cnt = (e < 2) ? TOK : g_cnt[e-2];
                int nmtE = (cnt + BM - 1) / BM;
                if (local < 64) { isCvt = true; isTile = false; bx = local; }
                else {
                    local -= 64;
                    bx = local / nmtE;
                    mBase = (local - bx*nmtE) * BM;
                }
            }
        } else {
            const int mt = item / (HD/BN);
            bx = item - mt*(HD/BN);
            e = g_mte[mt]; mBase = g_mtm[mt];
            cnt = (e < 2) ? TOK : g_cnt[e-2];
        }

        if (isTile) {
            // ---------------- GEMM tile ----------------
            const int nB = bx * BN;
            const __half* A; const __half* B; int lda, ldb;
            if (MODE == 1) { A = g_x16;                  lda = HD; B = g_wgu + (size_t)e*HD*N2; ldb = N2; }
            else           { A = g_h + (size_t)e*TOK*ID; lda = ID; B = g_wd  + (size_t)e*ID*HD; ldb = HD; }

            if (MODE == 1) {
                // wait for this strip's convert (its item strictly precedes ours -> no deadlock)
                if (tid == 0) {
                    while (atomicAdd(&g_sflag[e*64 + bx], 0) == 0) __nanosleep(64);
                }
                __syncthreads();
            }

            const __half* aPtr[4];
#pragma unroll
            for (int i = 0; i < 4; i++) {
                int slot = mBase + aR[i];
                int sc = (slot < cnt) ? slot : (cnt - 1);
                int row = (MODE == 1 && e >= 2) ? g_tok[(e-2)*TOK + sc] : sc;
                aPtr[i] = A + (size_t)row*lda + aC[i];
            }

            float acc[4][4][4];
#pragma unroll
            for (int mi = 0; mi < 4; mi++)
#pragma unroll
                for (int nt = 0; nt < 4; nt++)
#pragma unroll
                    for (int k = 0; k < 4; k++) acc[mi][nt][k] = 0.f;

            auto loadStage = [&](int st, int k0) {
                uint32_t base = sbase + (uint32_t)(st*STGH)*2;
#pragma unroll
                for (int i = 0; i < 4; i++)
                    cpa16(base + (uint32_t)(aR[i]*PA + aC[i])*2, aPtr[i] + k0);
#pragma unroll
                for (int i = 0; i < 4; i++)
                    cpa16(base + (uint32_t)(ASTG + bR[i]*PB + bC[i])*2,
                          B + (size_t)(k0 + bR[i])*ldb + nB + bC[i]);
                asm volatile("cp.async.commit_group;\n");
            };

            loadStage(0, 0);
            loadStage(1, BK);

            int st = 0;
            for (int it = 0; it < nIter; ++it) {
                if (it < nIter - 1) asm volatile("cp.async.wait_group 1;\n" ::: "memory");
                else                asm volatile("cp.async.wait_group 0;\n" ::: "memory");
                __syncthreads();

                if (it + 2 < nIter) {
                    int ns = st + 2; if (ns >= NSTAGE) ns -= NSTAGE;
                    loadStage(ns, (it + 2) * BK);
                }

                uint32_t aoff = sbase + (uint32_t)(st*STGH)*2;
                uint32_t boff = aoff + (uint32_t)ASTG*2;
#pragma unroll
                for (int ks = 0; ks < 4; ++ks) {
                    uint32_t af[4][4]; uint32_t bf[4][2];
#pragma unroll
                    for (int mi = 0; mi < 4; mi++) {
                        int row = wm*64 + mi*16 + (lane & 15);
                        int col = ks*16 + 8*(lane >> 4);
                        ldm4(af[mi][0], af[mi][1], af[mi][2], af[mi][3],
                             aoff + (uint32_t)(row*PA + col)*2);
                    }
#pragma unroll
                    for (int nj = 0; nj < 2; nj++) {
                        int row = ks*16 + (lane & 15);
                        int col = wn*32 + nj*16 + 8*(lane >> 4);
                        uint32_t r0, r1, r2, r3;
                        ldm4t(r0, r1, r2, r3, boff + (uint32_t)(row*PB + col)*2);
                        bf[2*nj][0] = r0; bf[2*nj][1] = r1;
                        bf[2*nj+1][0] = r2; bf[2*nj+1][1] = r3;
                    }
#pragma unroll
                    for (int mi = 0; mi < 4; mi++)
#pragma unroll
                        for (int nt = 0; nt < 4; nt++)
                            mma16816(acc[mi][nt], af[mi], bf[nt][0], bf[nt][1]);
                }
                if (++st == NSTAGE) st = 0;
            }

            // ---------------- epilogue ----------------
            const int gid = lane >> 2, t4 = lane & 3;
            if (MODE == 1) {
                __half* hbase = g_h + (size_t)e*TOK*ID;
#pragma unroll
                for (int mi = 0; mi < 4; mi++) {
                    int s0 = mBase + wm*64 + mi*16 + gid;
                    int s1 = s0 + 8;
                    bool v0 = s0 < cnt, v1 = s1 < cnt;
                    float w0 = 0.5f, w1 = 0.5f;
                    if (e >= 2) {
                        if (v0) w0 = g_wslot[(e-2)*TOK + s0];
                        if (v1) w1 = g_wslot[(e-2)*TOK + s1];
                    }
#pragma unroll
                    for (int nt = 0; nt < 4; nt++) {
                        int jh = (nB >> 1) + wn*16 + nt*4 + t4;
                        if (v0) {
                            float g = acc[mi][nt][0], u = acc[mi][nt][1];
                            hbase[(size_t)s0*ID + jh] = __float2half_rn(w0 * u * g / (1.f + __expf(-g)));
                        }
                        if (v1) {
                            float g = acc[mi][nt][2], u = acc[mi][nt][3];
                            hbase[(size_t)s1*ID + jh] = __float2half_rn(w1 * u * g / (1.f + __expf(-g)));
                        }
                    }
                }
            } else {
#pragma unroll
                for (int mi = 0; mi < 4; mi++) {
                    int s0 = mBase + wm*64 + mi*16 + gid;
                    int s1 = s0 + 8;
                    bool v0 = s0 < cnt, v1 = s1 < cnt;
                    int t0 = 0, t1 = 0;
                    if (e < 2) { t0 = s0; t1 = s1; }
                    else {
                        if (v0) t0 = g_tok[(e-2)*TOK + s0];
                        if (v1) t1 = g_tok[(e-2)*TOK + s1];
                    }
#pragma unroll
                    for (int nt = 0; nt < 4; nt++) {
                        int gn = nB + wn*32 + nt*8 + 2*t4;
                        if (v0) redv2(outp + (size_t)t0*HD + gn, acc[mi][nt][0], acc[mi][nt][1]);
                        if (v1) redv2(outp + (size_t)t1*HD + gn, acc[mi][nt][2], acc[mi][nt][3]);
                    }
                }
            }
        } else if (isCvt) {
            // ---------------- wgu convert strip (e, bx): 64 fp32 cols of Wg+Wu ----------------
            const float4* g4 = (const float4*)((e < 2) ? wgS + (size_t)e*HD*ID : wgR + (size_t)(e-2)*HD*ID);
            const float4* u4 = (const float4*)((e < 2) ? wuS + (size_t)e*HD*ID : wuR + (size_t)(e-2)*HD*ID);
            __half* dst = g_wgu + (size_t)e*HD*N2 + bx*128;
#pragma unroll 4
            for (int i = tid; i < HD*16; i += 256) {
                int row = i >> 4, c4 = i & 15;
                float4 g = g4[row*(ID/4) + bx*16 + c4];
                float4 u = u4[row*(ID/4) + bx*16 + c4];
                uint4 o;
                o.x = h2u(__floats2half2_rn(g.x, u.x));
                o.y = h2u(__floats2half2_rn(g.y, u.y));
                o.z = h2u(__floats2half2_rn(g.z, u.z));
                o.w = h2u(__floats2half2_rn(g.w, u.w));
                *(uint4*)(dst + (size_t)row*N2 + 8*c4) = o;
            }
            __threadfence();
            __syncthreads();
            if (tid == 0) atomicExch(&g_sflag[e*64 + bx], 1);
        } else if (isWd) {
            // ---------------- Wd fp32->fp16 chunk (tail filler) ----------------
            const long base = (long)(item - g_eoff[NE]) * CHF4;   // f4 index into 8-expert Wd
            const float4* src; long off;
            if (base < NS4) { src = (const float4*)wdS; off = base; }
            else            { src = (const float4*)wdR; off = base - NS4; }
            uint4* d4 = (uint4*)g_wd;
            const long o2 = base >> 1;                    // uint4 output index
#pragma unroll 4
            for (int i = tid; i < CHF4/2; i += 256) {
                float4 a = src[off + 2*i], b = src[off + 2*i + 1];
                uint4 o;
                o.x = h2u(__floats2half2_rn(a.x, a.y));
                o.y = h2u(__floats2half2_rn(a.z, a.w));
                o.z = h2u(__floats2half2_rn(b.x, b.y));
                o.w = h2u(__floats2half2_rn(b.z, b.w));
                d4[o2 + i] = o;
            }
        }
        __syncthreads();   // all smem reads done before next item's s_item write / loads
    }
}

// ---------------- host ----------------
extern "C" void kernel_launch(void* const* d_in, const int* in_sizes, int n_in,
                              void* d_out, int out_size) {
    const float* x    = (const float*)d_in[0];
    const float* Wg_s = (const float*)d_in[1];
    const float* Wu_s = (const float*)d_in[2];
    const float* Wd_s = (const float*)d_in[3];
    const float* Wg_r = (const float*)d_in[4];
    const float* Wu_r = (const float*)d_in[5];
    const float* Wd_r = (const float*)d_in[6];
    const float* Wr   = (const float*)d_in[7];
    const float* rb   = (const float*)d_in[8];
    float* out = (float*)d_out;

    cudaMemsetAsync(out, 0, (size_t)out_size * sizeof(float));

    k_cvt_x<<<384, 256>>>(x, (long)TOK*HD/8);
    k_router<<<TOK/8, 256>>>(x, Wr, rb);
    k_plan<<<1, 32>>>();

    cudaFuncSetAttribute(k_gemm<1>, cudaFuncAttributeMaxDynamicSharedMemorySize, SMEMSZ);
    cudaFuncSetAttribute(k_gemm<2>, cudaFuncAttributeMaxDynamicSharedMemorySize, SMEMSZ);

    // GEMM1 queue: per expert [wgu converts][gate/up tiles], then Wd-convert chunks
    k_gemm<1><<<NWORK, 256, SMEMSZ>>>(nullptr, Wd_s, Wd_r, Wg_s, Wu_s, Wg_r, Wu_r);
    // GEMM2 queue: down-proj tiles
    k_gemm<2><<<NWORK, 256, SMEMSZ>>>(out, nullptr, nullptr, nullptr, nullptr, nullptr, nullptr);
}